// round 1
// baseline (speedup 1.0000x reference)
#include <cuda_runtime.h>
#include <cstdint>

// Problem constants (fixed by the reference's setup_inputs)
#define NN 13          // nodes incl. driver
#define NR 12          // real (output) nodes
#define NB 4           // batch
#define NC 3           // channels
#define NH 256
#define NW 256
#define NE 37          // edges
#define KK 4           // kernel size
#define HW (NH*NW)     // 65536
#define PLANE (NC*HW)  // per (node,b) plane: 3*65536

// Scratch: sigmoid activations for all 13 nodes. 13*4*3*65536 floats = ~41 MB.
__device__ float g_act[(size_t)NN * NB * PLANE];

// ---------------------------------------------------------------------------
// Kernel 1: elementwise sigmoid, float4-vectorized
// ---------------------------------------------------------------------------
__global__ void sigmoid_kernel(const float* __restrict__ states, int n4) {
    int i = blockIdx.x * blockDim.x + threadIdx.x;
    if (i < n4) {
        float4 v = reinterpret_cast<const float4*>(states)[i];
        v.x = 1.f / (1.f + __expf(-v.x));
        v.y = 1.f / (1.f + __expf(-v.y));
        v.z = 1.f / (1.f + __expf(-v.z));
        v.w = 1.f / (1.f + __expf(-v.w));
        reinterpret_cast<float4*>(g_act)[i] = v;
    }
}

// ---------------------------------------------------------------------------
// Kernel 2: fused per-dest conv + segment mean.
// Block = (dest node v, batch b, 32x32 output tile). 256 threads.
// Thread (ty = tid>>3 in 0..31 rows, tx = tid&7) computes a 1x4 strip of
// outputs (w = 4*tx .. 4*tx+3) for all 3 output channels.
// SAME padding for K=4: pad_lo = 1, pad_hi = 2 -> input halo rows/cols
// [h0-1, h0+33] i.e. a 35x35 tile per cin.
// ---------------------------------------------------------------------------
#define TILE 32
#define HALO 35          // TILE + K - 1
#define SSTR 37          // smem row stride (floats) -> conflict-free pattern

__global__ __launch_bounds__(256, 2)
void conv_kernel(const float* __restrict__ weights,   // [E][3][3][4][4]
                 const float* __restrict__ bias,      // [E][3]
                 const int*   __restrict__ edge_src,
                 const int*   __restrict__ edge_dst,
                 float*       __restrict__ out)       // [12][4][3][256][256]
{
    __shared__ float sx[NC][HALO][SSTR];
    __shared__ float sw[NC * NC * KK * KK];  // 144
    __shared__ float sb[NC];
    __shared__ int   s_src[NE], s_dst[NE];

    const int tid = threadIdx.x;
    if (tid < NE) { s_src[tid] = edge_src[tid]; s_dst[tid] = edge_dst[tid]; }
    __syncthreads();

    const int v  = blockIdx.z;
    const int b  = blockIdx.y;
    const int h0 = (blockIdx.x >> 3) * TILE;
    const int w0 = (blockIdx.x & 7)  * TILE;

    const int ty = tid >> 3;        // 0..31 output row within tile
    const int tx = tid & 7;
    const int wl = tx * 4;          // output col start within tile

    float acc[4][NC];
    #pragma unroll
    for (int p = 0; p < 4; p++)
        #pragma unroll
        for (int c = 0; c < NC; c++) acc[p][c] = 0.f;
    float bsum[NC] = {0.f, 0.f, 0.f};

    int ne = 0;
    for (int e = 0; e < NE; e++) {
        if (s_dst[e] != v) continue;   // uniform across block
        ne++;
        const int src = s_src[e];
        const float* ap = g_act + ((size_t)src * NB + b) * PLANE;

        __syncthreads();   // protect sx/sw from previous edge's readers

        // cooperative halo load: 3 * 35 * 35 = 3675 elements
        for (int idx = tid; idx < NC * HALO * HALO; idx += 256) {
            int cin = idx / (HALO * HALO);
            int rem = idx - cin * (HALO * HALO);
            int r   = rem / HALO;
            int cc  = rem - r * HALO;
            int gh  = h0 - 1 + r;
            int gw  = w0 - 1 + cc;
            float val = 0.f;
            if ((unsigned)gh < (unsigned)NH && (unsigned)gw < (unsigned)NW)
                val = __ldg(ap + cin * HW + gh * NW + gw);
            sx[cin][r][cc] = val;
        }
        if (tid < NC * NC * KK * KK) sw[tid] = weights[e * (NC*NC*KK*KK) + tid];
        if (tid < NC)                sb[tid] = bias[e * NC + tid];
        __syncthreads();

        #pragma unroll
        for (int cin = 0; cin < NC; cin++) {
            #pragma unroll
            for (int kh = 0; kh < KK; kh++) {
                float x[7];
                #pragma unroll
                for (int j = 0; j < 7; j++) x[j] = sx[cin][ty + kh][wl + j];
                #pragma unroll
                for (int kw = 0; kw < KK; kw++) {
                    #pragma unroll
                    for (int co = 0; co < NC; co++) {
                        float wv = sw[co * 48 + cin * 16 + kh * 4 + kw];
                        #pragma unroll
                        for (int p = 0; p < 4; p++)
                            acc[p][co] = fmaf(x[kw + p], wv, acc[p][co]);
                    }
                }
            }
        }
        #pragma unroll
        for (int c = 0; c < NC; c++) bsum[c] += sb[c];
    }

    const float inv = 1.f / (float)ne;
    const size_t obase = ((size_t)v * NB + b) * PLANE + (size_t)(h0 + ty) * NW + (w0 + wl);
    #pragma unroll
    for (int co = 0; co < NC; co++) {
        float4 r;
        r.x = (acc[0][co] + bsum[co]) * inv;
        r.y = (acc[1][co] + bsum[co]) * inv;
        r.z = (acc[2][co] + bsum[co]) * inv;
        r.w = (acc[3][co] + bsum[co]) * inv;
        *reinterpret_cast<float4*>(out + obase + (size_t)co * HW) = r;
    }
}

// ---------------------------------------------------------------------------
extern "C" void kernel_launch(void* const* d_in, const int* in_sizes, int n_in,
                              void* d_out, int out_size)
{
    const float* states   = (const float*)d_in[0];  // [13,4,3,256,256]
    const float* weights  = (const float*)d_in[1];  // [37,3,3,4,4]
    const float* bias     = (const float*)d_in[2];  // [37,3]
    const int*   edge_src = (const int*)  d_in[3];  // [37]
    const int*   edge_dst = (const int*)  d_in[4];  // [37]
    float*       out      = (float*)      d_out;    // [12,4,3,256,256]

    // Kernel 1: sigmoid of all node states into g_act
    const int n  = NN * NB * PLANE;          // 10,223,616 (divisible by 4)
    const int n4 = n / 4;
    sigmoid_kernel<<<(n4 + 255) / 256, 256>>>(states, n4);

    // Kernel 2: per-dest fused conv + mean
    dim3 grid(64, NB, NR);                   // 8x8 tiles, 4 batch, 12 nodes
    conv_kernel<<<grid, 256>>>(weights, bias, edge_src, edge_dst, out);
}